// round 16
// baseline (speedup 1.0000x reference)
#include <cuda_runtime.h>
#include <cuda_bf16.h>
#include <cstdint>

#define N_BOXES   147456
#define NUM_POST  300
#define IOU_THR   0.7f
#define SCORE_THR 0.997f
#define CAP       1024
#define MASK_W    32
#define NBLOCKS   148
#define NTHREADS  512

// Device-global scratch (zero-init at load; finisher resets mutable state).
__device__ unsigned int       g_count;
__device__ unsigned int       g_arrive1;
__device__ unsigned int       g_arrive2;
__device__ unsigned long long g_ckey[CAP];
__device__ float4             g_cbox[CAP];    // unsorted (decode order)
__device__ int                g_order[CAP];   // sorted pos -> unsorted id
__device__ float4             g_sbox[CAP];    // boxes in sorted order
__device__ unsigned int       g_mask[CAP * MASK_W];  // rows SORTED, bits UNSORTED

__global__ void __launch_bounds__(NTHREADS, 1)
fused_rpn_kernel(const float* __restrict__ scores,
                 const float* __restrict__ deltas,
                 const float* __restrict__ anchors,
                 const int*   __restrict__ p_h,
                 const int*   __restrict__ p_w,
                 float*       __restrict__ out)
{
    extern __shared__ char smem_raw[];
    unsigned int* s_rows  = (unsigned int*)smem_raw;                          // 128 KB
    float4*       s_boxes = (float4*)(smem_raw + CAP * MASK_W * 4);           // 16 KB
    int*          s_ew    = (int*)(smem_raw + CAP * MASK_W * 4 + CAP * 16);   // 4 KB
    unsigned int* s_eb    = (unsigned int*)(smem_raw + CAP*MASK_W*4 + CAP*20);// 4 KB
    int*          s_klist = (int*)(smem_raw + CAP * MASK_W * 4 + CAP * 24);   // 1.2 KB
    __shared__ unsigned int s_last;
    __shared__ unsigned int s_cnt;     // per-block candidate count
    __shared__ unsigned int s_base;    // block's reserved range start

    const int tid  = threadIdx.x;
    const int lane = tid & 31;
    const int wid  = tid >> 5;
    const int gt   = blockIdx.x * NTHREADS + tid;

    // ---------------- Phase 1: decode + filter, two-level append ------------
    if (tid == 0) s_cnt = 0u;
    if (blockIdx.x == NBLOCKS - 1 && tid < NUM_POST)
        reinterpret_cast<float4*>(out)[tid] = make_float4(0.f, 0.f, 0.f, 0.f);
    __syncthreads();

    // Decode up to 4 candidates into registers.
    int myn = 0;
    float4             mybox[4];
    unsigned long long mykey[4];

    if (gt < N_BOXES / 4) {
        float4 s4 = reinterpret_cast<const float4*>(scores)[gt];
        if (fmaxf(fmaxf(s4.x, s4.y), fmaxf(s4.z, s4.w)) > SCORE_THR) {
            const float H = (float)(*p_h);
            const float W = (float)(*p_w);
            const int base = gt * 4;
            float sv[4] = {s4.x, s4.y, s4.z, s4.w};
            #pragma unroll
            for (int k = 0; k < 4; ++k) {
                float s = sv[k];
                if (s <= SCORE_THR) continue;
                int i = base + k;

                float4 a = reinterpret_cast<const float4*>(anchors)[i];
                float4 d = reinterpret_cast<const float4*>(deltas)[i];

                float ha  = a.z - a.x;
                float wa  = a.w - a.y;
                float cya = a.x + 0.5f * ha;
                float cxa = a.y + 0.5f * wa;

                float cy = d.x * ha + cya;
                float cx = d.y * wa + cxa;
                float h  = ha * expf(d.z);
                float w  = wa * expf(d.w);

                float y1 = fminf(fmaxf(cy - 0.5f * h, 0.0f), H);
                float x1 = fminf(fmaxf(cx - 0.5f * w, 0.0f), W);
                float y2 = fminf(fmaxf(cy + 0.5f * h, 0.0f), H);
                float x2 = fminf(fmaxf(cx + 0.5f * w, 0.0f), W);

                unsigned int sb = __float_as_uint(s);
                mykey[myn] = ((unsigned long long)sb << 32) |
                             (unsigned long long)(~(unsigned int)i);
                mybox[myn] = make_float4(y1, x1, y2, x2);
                ++myn;
            }
        }
    }

    // Two-level slot reservation: smem count, then ONE global atomic/block.
    unsigned int local = 0u;
    if (myn) local = atomicAdd(&s_cnt, (unsigned int)myn);
    __syncthreads();
    if (tid == 0) {
        s_base = s_cnt ? atomicAdd(&g_count, s_cnt) : 0u;
    }
    __syncthreads();
    {
        unsigned int pos = s_base + local;
        #pragma unroll
        for (int u = 0; u < 4; ++u) {
            if (u < myn && pos + u < CAP) {
                g_ckey[pos + u] = mykey[u];
                g_cbox[pos + u] = mybox[u];
            }
        }
    }

    // ---------------- Grid barrier 1 (hot spin, 1 thread/block) ------------
    __syncthreads();
    if (tid == 0) {
        __threadfence();
        atomicAdd(&g_arrive1, 1u);
        volatile unsigned int* va = &g_arrive1;
        while (*va < NBLOCKS) { }
        __threadfence();
    }
    __syncthreads();

    // ---------------- Phase 2: mask row + rank; write SORTED ----------------
    const int count  = min((int)g_count, CAP);
    const int nwords = (count + 31) >> 5;

    {
        int c = blockIdx.x + wid * NBLOCKS;     // one candidate per warp
        if (c < count) {
            float4 bc = g_cbox[c];
            float  ac = (bc.z - bc.x) * (bc.w - bc.y);
            unsigned long long kc = g_ckey[c];

            unsigned int myword = 0u;
            int r = 0;
            for (int jj = 0; jj < nwords; jj += 4) {
                unsigned long long kj[4];
                float4 bj[4];
                bool   val[4];
                #pragma unroll
                for (int u = 0; u < 4; ++u) {
                    int jw = jj + u;
                    int j  = (jw << 5) + lane;
                    val[u] = (jw < nwords) && (j < count);
                    if (val[u]) {
                        kj[u] = __ldg(&g_ckey[j]);
                        bj[u] = __ldg(&g_cbox[j]);
                    }
                }
                #pragma unroll
                for (int u = 0; u < 4; ++u) {
                    int jw = jj + u;
                    int j  = (jw << 5) + lane;
                    bool bit = false;
                    if (val[u]) {
                        r += (kj[u] > kc);
                        if (j != c) {
                            float4 b = bj[u];
                            float yy1 = fmaxf(bc.x, b.x);
                            float xx1 = fmaxf(bc.y, b.y);
                            float yy2 = fminf(bc.z, b.z);
                            float xx2 = fminf(bc.w, b.w);
                            float inter = fmaxf(yy2 - yy1, 0.0f) *
                                          fmaxf(xx2 - xx1, 0.0f);
                            float aj = (b.z - b.x) * (b.w - b.y);
                            float iou = inter / (ac + aj - inter + 1e-8f);
                            bit = (iou > IOU_THR);
                        }
                    }
                    if (jw < nwords) {
                        unsigned int w = __ballot_sync(0xffffffffu, bit);
                        if (lane == jw) myword = w;
                    }
                }
            }
            int rk = __reduce_add_sync(0xffffffffu, r);   // rank (all lanes)
            g_mask[(rk << 5) | lane] = myword;            // row at sorted pos
            if (lane == 0) {
                g_order[rk] = c;
                g_sbox[rk]  = bc;
            }
        }
    }

    // ---------------- Last-block-takes-over (no spin) -----------------------
    __syncthreads();
    if (tid == 0) {
        __threadfence();
        unsigned int old = atomicAdd(&g_arrive2, 1u);
        s_last = (old == NBLOCKS - 1) ? 1u : 0u;
    }
    __syncthreads();
    if (!s_last) return;
    __threadfence();   // acquire: all other blocks' writes now visible

    // ---------------- Phase 3 (finisher): coalesced staging + precompute ----
    for (int q = tid; q < count; q += NTHREADS) {
        s_boxes[q] = g_sbox[q];
        int e = g_order[q];
        s_ew[q] = e >> 5;              // suppressed-word index for position q
        s_eb[q] = 1u << (e & 31);      // bit within that word
    }
    for (int idx = tid; idx < (count << 5); idx += NTHREADS)
        s_rows[idx] = g_mask[idx];     // already sorted, no indirection
    __syncthreads();

    // ---------------- Warp-0 quad scan, single REDUX.OR per quad ------------
    if (tid < 32 && count > 0) {
        const int cm1 = count - 1;
        unsigned int supp = 0u;        // lane l = suppressed word l (unsorted ids)
        int nk = 0;

        int          ew[4];
        unsigned int eb[4];
        unsigned int r[4];
        #pragma unroll
        for (int u = 0; u < 4; ++u) {
            int q = (u < count) ? u : cm1;
            ew[u] = s_ew[q];
            eb[u] = s_eb[q];
            r[u]  = s_rows[(q << 5) | lane];
        }

        int p = 0;
        while (p < count && nk < NUM_POST) {
            // Prefetch next quad from SMEM (independent, overlaps resolve).
            int          ewn[4];
            unsigned int ebn[4];
            unsigned int rn[4];
            const int pn = p + 4;
            if (pn < count) {
                #pragma unroll
                for (int u = 0; u < 4; ++u) {
                    int q = pn + u; q = (q < cm1) ? q : cm1;
                    ewn[u] = s_ew[q];
                    ebn[u] = s_eb[q];
                    rn[u]  = s_rows[(q << 5) | lane];
                }
            }

            // Pack 4 self-tests (bits 0-3) + 6 cross-tests (bits 4-9).
            unsigned int pack = 0u;
            #pragma unroll
            for (int u = 0; u < 4; ++u)
                if ((lane == ew[u]) && (supp & eb[u]))
                    pack |= (1u << u);
            if ((lane == ew[1]) && (r[0] & eb[1])) pack |= 1u << 4; // x01
            if ((lane == ew[2]) && (r[0] & eb[2])) pack |= 1u << 5; // x02
            if ((lane == ew[3]) && (r[0] & eb[3])) pack |= 1u << 6; // x03
            if ((lane == ew[2]) && (r[1] & eb[2])) pack |= 1u << 7; // x12
            if ((lane == ew[3]) && (r[1] & eb[3])) pack |= 1u << 8; // x13
            if ((lane == ew[3]) && (r[2] & eb[3])) pack |= 1u << 9; // x23

            const unsigned int ub = __reduce_or_sync(0xffffffffu, pack);

            const bool h1 = (p + 1 < count);
            const bool h2 = (p + 2 < count);
            const bool h3 = (p + 3 < count);

            bool k0 = !(ub & 1u);
            bool k1 = h1 && !((ub >> 1) & 1u) && !(k0 && ((ub >> 4) & 1u));
            bool k2 = h2 && !((ub >> 2) & 1u) && !(k0 && ((ub >> 5) & 1u))
                                              && !(k1 && ((ub >> 7) & 1u));
            bool k3 = h3 && !((ub >> 3) & 1u) && !(k0 && ((ub >> 6) & 1u))
                                              && !(k1 && ((ub >> 8) & 1u))
                                              && !(k2 && ((ub >> 9) & 1u));

            // Cap at NUM_POST.
            int c0 = k0 ? 1 : 0;
            k1 = k1 && (nk + c0 < NUM_POST);
            int c1 = c0 + (k1 ? 1 : 0);
            k2 = k2 && (nk + c1 < NUM_POST);
            int c2 = c1 + (k2 ? 1 : 0);
            k3 = k3 && (nk + c2 < NUM_POST);
            int c3 = c2 + (k3 ? 1 : 0);

            supp |= (k0 ? r[0] : 0u) | (k1 ? r[1] : 0u)
                  | (k2 ? r[2] : 0u) | (k3 ? r[3] : 0u);

            if (lane == 0) {
                int q = nk;
                if (k0) s_klist[q++] = p;
                if (k1) s_klist[q++] = p + 1;
                if (k2) s_klist[q++] = p + 2;
                if (k3) s_klist[q++] = p + 3;
            }
            nk += c3;
            p = pn;
            #pragma unroll
            for (int u = 0; u < 4; ++u) {
                ew[u] = ewn[u]; eb[u] = ebn[u]; r[u] = rn[u];
            }
        }

        // Emit kept boxes from the sorted smem copy.
        for (int i = lane; i < nk; i += 32)
            reinterpret_cast<float4*>(out)[i] = s_boxes[s_klist[i]];

        if (lane == 0) {                 // reset for next graph replay
            g_count   = 0u;
            g_arrive1 = 0u;
            g_arrive2 = 0u;
        }
    }
}

// ---------------------------------------------------------------------------
extern "C" void kernel_launch(void* const* d_in, const int* in_sizes, int n_in,
                              void* d_out, int out_size)
{
    const float* scores  = (const float*)d_in[0];
    const float* deltas  = (const float*)d_in[1];
    const float* anchors = (const float*)d_in[2];
    const int*   p_h     = (const int*)d_in[3];
    const int*   p_w     = (const int*)d_in[4];
    float*       out     = (float*)d_out;

    const int smem_bytes = CAP * MASK_W * 4 + CAP * 16 + CAP * 4 + CAP * 4
                         + NUM_POST * 4;                        // 156848
    static bool attr_set = false;
    if (!attr_set) {
        cudaFuncSetAttribute(fused_rpn_kernel,
                             cudaFuncAttributeMaxDynamicSharedMemorySize,
                             smem_bytes);
        attr_set = true;
    }

    fused_rpn_kernel<<<NBLOCKS, NTHREADS, smem_bytes>>>(
        scores, deltas, anchors, p_h, p_w, out);
}

// round 17
// speedup vs baseline: 1.0749x; 1.0749x over previous
#include <cuda_runtime.h>
#include <cuda_bf16.h>
#include <cstdint>

#define N_BOXES   147456
#define NUM_POST  300
#define IOU_THR   0.7f
#define SCORE_THR 0.997f
#define CAP       1024
#define MASK_W    32
#define NBLOCKS   148
#define NTHREADS  512

// Device-global scratch (zero-init at load; finisher resets mutable state).
__device__ unsigned int       g_count;
__device__ unsigned int       g_arrive1;
__device__ unsigned int       g_arrive2;
__device__ unsigned long long g_ckey[CAP];
__device__ float4             g_cbox[CAP];    // unsorted (decode order)
__device__ int                g_order[CAP];   // sorted pos -> unsorted id
__device__ float4             g_sbox[CAP];    // boxes in sorted order
__device__ int                g_clean[CAP];   // sorted pos -> provably-kept flag
__device__ unsigned int       g_mask[CAP * MASK_W];  // rows SORTED, bits UNSORTED

__global__ void __launch_bounds__(NTHREADS, 1)
fused_rpn_kernel(const float* __restrict__ scores,
                 const float* __restrict__ deltas,
                 const float* __restrict__ anchors,
                 const int*   __restrict__ p_h,
                 const int*   __restrict__ p_w,
                 float*       __restrict__ out)
{
    extern __shared__ char smem_raw[];
    unsigned int* s_rows  = (unsigned int*)smem_raw;                          // 128 KB
    float4*       s_boxes = (float4*)(smem_raw + CAP * MASK_W * 4);           // 16 KB
    int*          s_ew    = (int*)(smem_raw + CAP * MASK_W * 4 + CAP * 16);   // 4 KB
    unsigned int* s_eb    = (unsigned int*)(smem_raw + CAP*MASK_W*4 + CAP*20);// 4 KB
    int*          s_clean = (int*)(smem_raw + CAP * MASK_W * 4 + CAP * 24);   // 4 KB
    int*          s_klist = (int*)(smem_raw + CAP * MASK_W * 4 + CAP * 28);   // 1.2 KB
    __shared__ unsigned int s_last;
    __shared__ unsigned int s_cnt;
    __shared__ unsigned int s_base;

    const int tid  = threadIdx.x;
    const int lane = tid & 31;
    const int wid  = tid >> 5;
    const int gt   = blockIdx.x * NTHREADS + tid;

    // ---------------- Phase 1: decode + filter, two-level append ------------
    if (tid == 0) s_cnt = 0u;
    if (blockIdx.x == NBLOCKS - 1 && tid < NUM_POST)
        reinterpret_cast<float4*>(out)[tid] = make_float4(0.f, 0.f, 0.f, 0.f);
    __syncthreads();

    int myn = 0;
    float4             mybox[4];
    unsigned long long mykey[4];

    if (gt < N_BOXES / 4) {
        float4 s4 = reinterpret_cast<const float4*>(scores)[gt];
        if (fmaxf(fmaxf(s4.x, s4.y), fmaxf(s4.z, s4.w)) > SCORE_THR) {
            const float H = (float)(*p_h);
            const float W = (float)(*p_w);
            const int base = gt * 4;
            float sv[4] = {s4.x, s4.y, s4.z, s4.w};
            #pragma unroll
            for (int k = 0; k < 4; ++k) {
                float s = sv[k];
                if (s <= SCORE_THR) continue;
                int i = base + k;

                float4 a = reinterpret_cast<const float4*>(anchors)[i];
                float4 d = reinterpret_cast<const float4*>(deltas)[i];

                float ha  = a.z - a.x;
                float wa  = a.w - a.y;
                float cya = a.x + 0.5f * ha;
                float cxa = a.y + 0.5f * wa;

                float cy = d.x * ha + cya;
                float cx = d.y * wa + cxa;
                float h  = ha * expf(d.z);
                float w  = wa * expf(d.w);

                float y1 = fminf(fmaxf(cy - 0.5f * h, 0.0f), H);
                float x1 = fminf(fmaxf(cx - 0.5f * w, 0.0f), W);
                float y2 = fminf(fmaxf(cy + 0.5f * h, 0.0f), H);
                float x2 = fminf(fmaxf(cx + 0.5f * w, 0.0f), W);

                unsigned int sb = __float_as_uint(s);
                mykey[myn] = ((unsigned long long)sb << 32) |
                             (unsigned long long)(~(unsigned int)i);
                mybox[myn] = make_float4(y1, x1, y2, x2);
                ++myn;
            }
        }
    }

    unsigned int local = 0u;
    if (myn) local = atomicAdd(&s_cnt, (unsigned int)myn);
    __syncthreads();
    if (tid == 0) s_base = s_cnt ? atomicAdd(&g_count, s_cnt) : 0u;
    __syncthreads();
    {
        unsigned int pos = s_base + local;
        #pragma unroll
        for (int u = 0; u < 4; ++u) {
            if (u < myn && pos + u < CAP) {
                g_ckey[pos + u] = mykey[u];
                g_cbox[pos + u] = mybox[u];
            }
        }
    }

    // ---------------- Grid barrier 1 (hot spin, 1 thread/block) ------------
    __syncthreads();
    if (tid == 0) {
        __threadfence();
        atomicAdd(&g_arrive1, 1u);
        volatile unsigned int* va = &g_arrive1;
        while (*va < NBLOCKS) { }
        __threadfence();
    }
    __syncthreads();

    // ---------------- Phase 2: mask row + rank + CLEAN flag; write SORTED ---
    const int count  = min((int)g_count, CAP);
    const int nwords = (count + 31) >> 5;

    {
        int c = blockIdx.x + wid * NBLOCKS;     // one candidate per warp
        if (c < count) {
            float4 bc = g_cbox[c];
            float  ac = (bc.z - bc.x) * (bc.w - bc.y);
            unsigned long long kc = g_ckey[c];

            unsigned int myword = 0u;
            int r = 0;
            bool conf = false;     // suppressed by ANY earlier-by-key candidate?
            for (int jj = 0; jj < nwords; jj += 4) {
                unsigned long long kj[4];
                float4 bj[4];
                bool   val[4];
                #pragma unroll
                for (int u = 0; u < 4; ++u) {
                    int jw = jj + u;
                    int j  = (jw << 5) + lane;
                    val[u] = (jw < nwords) && (j < count);
                    if (val[u]) {
                        kj[u] = __ldg(&g_ckey[j]);
                        bj[u] = __ldg(&g_cbox[j]);
                    }
                }
                #pragma unroll
                for (int u = 0; u < 4; ++u) {
                    int jw = jj + u;
                    int j  = (jw << 5) + lane;
                    bool bit = false;
                    if (val[u]) {
                        bool earlier = (kj[u] > kc);
                        r += earlier;
                        if (j != c) {
                            float4 b = bj[u];
                            float yy1 = fmaxf(bc.x, b.x);
                            float xx1 = fmaxf(bc.y, b.y);
                            float yy2 = fminf(bc.z, b.z);
                            float xx2 = fminf(bc.w, b.w);
                            float inter = fmaxf(yy2 - yy1, 0.0f) *
                                          fmaxf(xx2 - xx1, 0.0f);
                            float aj = (b.z - b.x) * (b.w - b.y);
                            float iou = inter / (ac + aj - inter + 1e-8f);
                            bit = (iou > IOU_THR);
                            conf = conf || (bit && earlier);
                        }
                    }
                    if (jw < nwords) {
                        unsigned int w = __ballot_sync(0xffffffffu, bit);
                        if (lane == jw) myword = w;
                    }
                }
            }
            int rk = __reduce_add_sync(0xffffffffu, r);   // rank (all lanes)
            unsigned int confAny = __ballot_sync(0xffffffffu, conf);
            g_mask[(rk << 5) | lane] = myword;            // row at sorted pos
            if (lane == 0) {
                g_order[rk] = c;
                g_sbox[rk]  = bc;
                g_clean[rk] = (confAny == 0u) ? 1 : 0;    // provably kept
            }
        }
    }

    // ---------------- Last-block-takes-over (no spin) -----------------------
    __syncthreads();
    if (tid == 0) {
        __threadfence();
        unsigned int old = atomicAdd(&g_arrive2, 1u);
        s_last = (old == NBLOCKS - 1) ? 1u : 0u;
    }
    __syncthreads();
    if (!s_last) return;
    __threadfence();   // acquire: all other blocks' writes now visible

    // ---------------- Phase 3 (finisher): coalesced staging -----------------
    for (int q = tid; q < count; q += NTHREADS) {
        s_boxes[q] = g_sbox[q];
        int e = g_order[q];
        s_ew[q]    = e >> 5;
        s_eb[q]    = 1u << (e & 31);
        s_clean[q] = g_clean[q];
    }
    for (int idx = tid; idx < (count << 5); idx += NTHREADS)
        s_rows[idx] = g_mask[idx];     // already sorted, no indirection
    __syncthreads();

    // ---------------- Warp-0 scan: sync only for non-clean candidates -------
    if (tid < 32 && count > 0) {
        unsigned int supp = 0u;        // lane l = suppressed word l (unsorted ids)
        int nk = 0;

        #pragma unroll 4
        for (int p = 0; p < count; ++p) {
            if (nk >= NUM_POST) break;
            unsigned int row = s_rows[(p << 5) | lane];   // indep of supp
            bool keep;
            if (s_clean[p]) {                              // warp-uniform
                keep = true;                               // provably kept
            } else {
                bool isSup = (lane == s_ew[p]) && (supp & s_eb[p]);
                keep = !__any_sync(0xffffffffu, isSup);
            }
            if (keep) {
                supp |= row;
                if (lane == 0) s_klist[nk] = p;
                ++nk;
            }
        }

        // Emit kept boxes from the sorted smem copy.
        for (int i = lane; i < nk; i += 32)
            reinterpret_cast<float4*>(out)[i] = s_boxes[s_klist[i]];

        if (lane == 0) {               // reset for next graph replay
            g_count   = 0u;
            g_arrive1 = 0u;
            g_arrive2 = 0u;
        }
    }
}

// ---------------------------------------------------------------------------
extern "C" void kernel_launch(void* const* d_in, const int* in_sizes, int n_in,
                              void* d_out, int out_size)
{
    const float* scores  = (const float*)d_in[0];
    const float* deltas  = (const float*)d_in[1];
    const float* anchors = (const float*)d_in[2];
    const int*   p_h     = (const int*)d_in[3];
    const int*   p_w     = (const int*)d_in[4];
    float*       out     = (float*)d_out;

    const int smem_bytes = CAP * MASK_W * 4 + CAP * 16 + CAP * 4 + CAP * 4
                         + CAP * 4 + NUM_POST * 4;              // 160944
    static bool attr_set = false;
    if (!attr_set) {
        cudaFuncSetAttribute(fused_rpn_kernel,
                             cudaFuncAttributeMaxDynamicSharedMemorySize,
                             smem_bytes);
        attr_set = true;
    }

    fused_rpn_kernel<<<NBLOCKS, NTHREADS, smem_bytes>>>(
        scores, deltas, anchors, p_h, p_w, out);
}